// round 14
// baseline (speedup 1.0000x reference)
#include <cuda_runtime.h>
#include <cstdint>

#define B_SZ  1024
#define DHALF 2048
#define DIN   4096
#define DOUT  1024
#define NLAB  128
#define KSPLIT 8

// Scratch (allocation-free rule: __device__ globals)
__device__ float g_x[B_SZ * DIN];               // relu(concat(sbj,obj))
__device__ float g_hidden[B_SZ * DOUT];         // relu(hidden)
__device__ float g_emb[B_SZ * DOUT];            // emb
__device__ float g_part[KSPLIT * B_SZ * NLAB];  // scores split-k partials

// ---------------------------------------------------------------------------
// helpers
// ---------------------------------------------------------------------------
__device__ __forceinline__ uint32_t smem_u32(const void* p) {
    uint32_t a;
    asm("{ .reg .u64 t; cvta.to.shared.u64 t, %1; cvt.u32.u64 %0, t; }"
        : "=r"(a) : "l"(p));
    return a;
}
#define CP16(dst, src) asm volatile("cp.async.cg.shared.global [%0], [%1], 16;" :: "r"(dst), "l"(src) : "memory")
#define CP_COMMIT()    asm volatile("cp.async.commit_group;" ::: "memory")

__device__ __forceinline__ void mma_tf32(float& c0, float& c1, float& c2, float& c3,
                                         uint32_t a0, uint32_t a1, uint32_t a2, uint32_t a3,
                                         uint32_t b0, uint32_t b1) {
    asm volatile(
        "mma.sync.aligned.m16n8k8.row.col.f32.tf32.tf32.f32 "
        "{%0,%1,%2,%3}, {%4,%5,%6,%7}, {%8,%9}, {%0,%1,%2,%3};"
        : "+f"(c0), "+f"(c1), "+f"(c2), "+f"(c3)
        : "r"(a0), "r"(a1), "r"(a2), "r"(a3), "r"(b0), "r"(b1));
}

// ---------------------------------------------------------------------------
// Prepass: g_x[m][k] = relu(concat(sbj,obj))
// ---------------------------------------------------------------------------
__global__ __launch_bounds__(256)
void relu_cat_kernel(const float* __restrict__ sbj, const float* __restrict__ obj,
                     float* __restrict__ x)
{
    const int idx = blockIdx.x * 256 + threadIdx.x;
    const int row = idx >> 10;
    const int c4  = idx & 1023;
    const int col = c4 * 4;
    const float* src = (col < DHALF) ? &sbj[(size_t)row * DHALF + col]
                                     : &obj[(size_t)row * DHALF + col - DHALF];
    float4 v = *reinterpret_cast<const float4*>(src);
    v.x = fmaxf(v.x, 0.f); v.y = fmaxf(v.y, 0.f);
    v.z = fmaxf(v.z, 0.f); v.w = fmaxf(v.w, 0.f);
    *reinterpret_cast<float4*>(&x[(size_t)row * DIN + col]) = v;
}

// ---------------------------------------------------------------------------
// tf32 tensor GEMM: C = act(A @ W + bias)
// CTA tile 64x64, 256 threads = 8 warps. Intra-CTA K-SPLIT:
//   warp quad q = wid&3 -> warp tile 32x32 at (wm,wn); kw = wid>>2 picks
//   k8 in {kw*16, kw*16+8} of each BK=32 stage. Two warps per output tile
//   accumulate privately; one smem reduction at the end.
// 3-stage cp.async ring (measured-best), ONE __syncthreads per stage.
// Bank-clean: As stride 36 (4*l4+lq perm), Bs stride 72 (8*lq+l4 perm).
// Reduction scratch: 4 quads x 32 lanes x stride 36 = 4608 floats = stage 0.
// ---------------------------------------------------------------------------
#define BM 64
#define BN 64
#define BK 32
#define AS_STR 36
#define BS_STR 72
#define AS_SZ  (BM * AS_STR)
#define BS_SZ  (BK * BS_STR)
#define STG_FL (AS_SZ + BS_SZ)      // 4608 floats
#define STG_BY (STG_FL * 4)         // 18432 bytes
#define NSTAGE 3
#define GEMM_SMEM (NSTAGE * STG_BY) // 55296

template <int RELU>
__global__ __launch_bounds__(256, 2)
void gemm_tc(const float* __restrict__ A, const float* __restrict__ Wmat,
             const float* __restrict__ bias, float* __restrict__ Cout, int K)
{
    extern __shared__ float sm[];
    const int T = K / BK;

    const int tid  = threadIdx.x;
    const int wid  = tid >> 5;
    const int lane = tid & 31;
    const int lq   = lane & 3;
    const int l4   = lane >> 2;

    const int m0 = blockIdx.y * BM;
    const int n0 = blockIdx.x * BN;
    const int wq = wid & 3;           // output quad
    const int kw = wid >> 2;          // k-half (0 or 1)
    const int wm = (wq >> 1) * 32;
    const int wn = (wq & 1) * 32;

    // fills with 256 threads: A tile 512 f4 -> 2/thread; B tile 512 f4 -> 2/thread
    const int ar0 = tid >> 3, ac = tid & 7;     // rows ar0, ar0+32
    const int br0 = tid >> 4, bc = tid & 15;    // rows br0, br0+16

    const uint32_t smBase = smem_u32(sm);
    const uint32_t aD0 = smBase + (uint32_t)(ar0 * AS_STR + ac * 4) * 4;
    const uint32_t aD1 = smBase + (uint32_t)((ar0 + 32) * AS_STR + ac * 4) * 4;
    const uint32_t bD0 = smBase + (uint32_t)(AS_SZ + br0 * BS_STR + bc * 4) * 4;
    const uint32_t bD1 = smBase + (uint32_t)(AS_SZ + (br0 + 16) * BS_STR + bc * 4) * 4;

    const float* aS0 = &A[(size_t)(m0 + ar0) * K + ac * 4];
    const float* aS1 = &A[(size_t)(m0 + ar0 + 32) * K + ac * 4];
    const float* bS0 = &Wmat[(size_t)br0 * DOUT + n0 + bc * 4];
    const float* bS1 = &Wmat[(size_t)(br0 + 16) * DOUT + n0 + bc * 4];

    auto issue = [&](int s) {
        const uint32_t off = (uint32_t)s * STG_BY;
        CP16(aD0 + off, aS0);
        CP16(aD1 + off, aS1);
        CP16(bD0 + off, bS0);
        CP16(bD1 + off, bS1);
        aS0 += BK; aS1 += BK;
        bS0 += (size_t)BK * DOUT; bS1 += (size_t)BK * DOUT;
    };

    float acc[2][4][4];
    #pragma unroll
    for (int mi = 0; mi < 2; mi++)
        #pragma unroll
        for (int nj = 0; nj < 4; nj++)
            #pragma unroll
            for (int r = 0; r < 4; r++) acc[mi][nj][r] = 0.f;

    issue(0); CP_COMMIT();
    issue(1); CP_COMMIT();

    int buf = 0, sNext = 2;
    const int kbase = kw * 16;        // this warp's k8 offsets: kbase, kbase+8

    for (int t = 0; t < T; t++) {
        asm volatile("cp.async.wait_group 1;" ::: "memory");
        __syncthreads();

        if (t + 2 < T) issue(sNext);
        CP_COMMIT();    // exactly one group per iteration

        const float* Ab = sm + buf * STG_FL;
        const float* Bb = Ab + AS_SZ;

        #pragma unroll
        for (int kk = 0; kk < 2; kk++) {
            const int k8 = kbase + kk * 8;
            uint32_t a[2][4];
            #pragma unroll
            for (int mi = 0; mi < 2; mi++) {
                const int R = wm + mi * 16 + l4;
                a[mi][0] = __float_as_uint(Ab[R * AS_STR + k8 + lq]);
                a[mi][1] = __float_as_uint(Ab[(R + 8) * AS_STR + k8 + lq]);
                a[mi][2] = __float_as_uint(Ab[R * AS_STR + k8 + lq + 4]);
                a[mi][3] = __float_as_uint(Ab[(R + 8) * AS_STR + k8 + lq + 4]);
            }
            uint32_t b[4][2];
            #pragma unroll
            for (int nj = 0; nj < 4; nj++) {
                const int Cn = wn + nj * 8 + l4;
                b[nj][0] = __float_as_uint(Bb[(k8 + lq) * BS_STR + Cn]);
                b[nj][1] = __float_as_uint(Bb[(k8 + lq + 4) * BS_STR + Cn]);
            }
            #pragma unroll
            for (int mi = 0; mi < 2; mi++)
                #pragma unroll
                for (int nj = 0; nj < 4; nj++)
                    mma_tf32(acc[mi][nj][0], acc[mi][nj][1],
                             acc[mi][nj][2], acc[mi][nj][3],
                             a[mi][0], a[mi][1], a[mi][2], a[mi][3],
                             b[nj][0], b[nj][1]);
        }

        buf   = (buf == NSTAGE - 1) ? 0 : buf + 1;
        sNext = (sNext == NSTAGE - 1) ? 0 : sNext + 1;
    }

    // ---- intra-CTA k-split reduction: kw=1 partials -> kw=0 warps ----
    // scratch: per quad 32 lanes x 36-float rows (16B aligned, bank-clean .128)
    __syncthreads();   // all compute done; stage smem reusable
    float* red = sm;   // 4*32*36 = 4608 floats = exactly stage 0
    const float4* accv = reinterpret_cast<const float4*>(&acc[0][0][0]);
    float* myrow = red + (wq * 32 + lane) * 36;
    if (kw == 1) {
        #pragma unroll
        for (int q = 0; q < 8; q++)
            *reinterpret_cast<float4*>(myrow + q * 4) = accv[q];
    }
    __syncthreads();

    if (kw == 0) {
        float* af = &acc[0][0][0];
        #pragma unroll
        for (int q = 0; q < 8; q++) {
            float4 p = *reinterpret_cast<const float4*>(myrow + q * 4);
            af[q * 4 + 0] += p.x;
            af[q * 4 + 1] += p.y;
            af[q * 4 + 2] += p.z;
            af[q * 4 + 3] += p.w;
        }

        // epilogue: bias (+relu)
        #pragma unroll
        for (int mi = 0; mi < 2; mi++) {
            #pragma unroll
            for (int nj = 0; nj < 4; nj++) {
                const int col = n0 + wn + nj * 8 + lq * 2;
                const float bb0 = bias[col];
                const float bb1 = bias[col + 1];
                const int row = m0 + wm + mi * 16 + l4;
                float o0 = acc[mi][nj][0] + bb0;
                float o1 = acc[mi][nj][1] + bb1;
                float o2 = acc[mi][nj][2] + bb0;
                float o3 = acc[mi][nj][3] + bb1;
                if (RELU) {
                    o0 = fmaxf(o0, 0.f); o1 = fmaxf(o1, 0.f);
                    o2 = fmaxf(o2, 0.f); o3 = fmaxf(o3, 0.f);
                }
                float2 p0 = {o0, o1};
                float2 p1 = {o2, o3};
                *reinterpret_cast<float2*>(&Cout[(size_t)row * DOUT + col])       = p0;
                *reinterpret_cast<float2*>(&Cout[(size_t)(row + 8) * DOUT + col]) = p1;
            }
        }
    }
}

// ---------------------------------------------------------------------------
// Scores split-k x8 (unchanged control): partial[q][b][l]
// ---------------------------------------------------------------------------
#define LS_STR 68
#define SC_STG (NLAB * LS_STR + 8 * LS_STR)     // 9248 floats
#define SC_SMEM (2 * SC_STG * 4)                // 73984 bytes
#define NCHUNK_Q ((DOUT / KSPLIT) / 64)         // 2

__global__ __launch_bounds__(256)
void scores_part_kernel(const float* __restrict__ labels,
                        const float* __restrict__ emb,
                        float* __restrict__ part)
{
    extern __shared__ float sm[];
    const int tid = threadIdx.x;
    const int b0  = blockIdx.x * 8;
    const int kh  = blockIdx.y * (DOUT / KSPLIT);
    const int l   = tid & 127;
    const int bg  = tid >> 7;

    const uint32_t smBase = smem_u32(sm);
    const int lr = tid >> 4, lc = tid & 15;

    auto issue = [&](int c, int buf) {
        const int k0 = kh + c * 64;
        const uint32_t off = (uint32_t)buf * (SC_STG * 4);
        #pragma unroll
        for (int j = 0; j < 8; j++) {
            const int row = lr + j * 16;
            CP16(smBase + off + (uint32_t)(row * LS_STR + lc * 4) * 4,
                 &labels[(size_t)row * DOUT + k0 + lc * 4]);
        }
        if (tid < 128) {
            const int row = tid >> 4, c4 = tid & 15;
            CP16(smBase + off + (uint32_t)(NLAB * LS_STR + row * LS_STR + c4 * 4) * 4,
                 &emb[(size_t)(b0 + row) * DOUT + k0 + c4 * 4]);
        }
    };

    float acc0 = 0.f, acc1 = 0.f, acc2 = 0.f, acc3 = 0.f;

    issue(0, 0); CP_COMMIT();

    for (int c = 0; c < NCHUNK_Q; c++) {
        const int buf = c & 1;
        if (c + 1 < NCHUNK_Q) { issue(c + 1, buf ^ 1); }
        CP_COMMIT();
        asm volatile("cp.async.wait_group 1;" ::: "memory");
        __syncthreads();

        const float* Sb = sm + buf * SC_STG;
        const float4* Lp = reinterpret_cast<const float4*>(Sb + l * LS_STR);
        const float* Ep = Sb + NLAB * LS_STR + (bg * 4) * LS_STR;

        #pragma unroll
        for (int k4 = 0; k4 < 16; k4++) {
            const float4 lv = Lp[k4];
            const float4 e0 = *reinterpret_cast<const float4*>(Ep + 0 * LS_STR + k4 * 4);
            const float4 e1 = *reinterpret_cast<const float4*>(Ep + 1 * LS_STR + k4 * 4);
            const float4 e2 = *reinterpret_cast<const float4*>(Ep + 2 * LS_STR + k4 * 4);
            const float4 e3 = *reinterpret_cast<const float4*>(Ep + 3 * LS_STR + k4 * 4);
            float d;
            d = fmaxf(lv.x - e0.x, 0.f); acc0 = fmaf(d, d, acc0);
            d = fmaxf(lv.y - e0.y, 0.f); acc0 = fmaf(d, d, acc0);
            d = fmaxf(lv.z - e0.z, 0.f); acc0 = fmaf(d, d, acc0);
            d = fmaxf(lv.w - e0.w, 0.f); acc0 = fmaf(d, d, acc0);
            d = fmaxf(lv.x - e1.x, 0.f); acc1 = fmaf(d, d, acc1);
            d = fmaxf(lv.y - e1.y, 0.f); acc1 = fmaf(d, d, acc1);
            d = fmaxf(lv.z - e1.z, 0.f); acc1 = fmaf(d, d, acc1);
            d = fmaxf(lv.w - e1.w, 0.f); acc1 = fmaf(d, d, acc1);
            d = fmaxf(lv.x - e2.x, 0.f); acc2 = fmaf(d, d, acc2);
            d = fmaxf(lv.y - e2.y, 0.f); acc2 = fmaf(d, d, acc2);
            d = fmaxf(lv.z - e2.z, 0.f); acc2 = fmaf(d, d, acc2);
            d = fmaxf(lv.w - e2.w, 0.f); acc2 = fmaf(d, d, acc2);
            d = fmaxf(lv.x - e3.x, 0.f); acc3 = fmaf(d, d, acc3);
            d = fmaxf(lv.y - e3.y, 0.f); acc3 = fmaf(d, d, acc3);
            d = fmaxf(lv.z - e3.z, 0.f); acc3 = fmaf(d, d, acc3);
            d = fmaxf(lv.w - e3.w, 0.f); acc3 = fmaf(d, d, acc3);
        }
        __syncthreads();
    }

    float* dst = part + (size_t)blockIdx.y * (B_SZ * NLAB);
    dst[(size_t)(b0 + bg * 4 + 0) * NLAB + l] = acc0;
    dst[(size_t)(b0 + bg * 4 + 1) * NLAB + l] = acc1;
    dst[(size_t)(b0 + bg * 4 + 2) * NLAB + l] = acc2;
    dst[(size_t)(b0 + bg * 4 + 3) * NLAB + l] = acc3;
}

__global__ __launch_bounds__(256)
void scores_reduce_kernel(const float* __restrict__ part, float* __restrict__ out)
{
    const int idx = blockIdx.x * 256 + threadIdx.x;   // 0 .. 131071
    float s = 0.f;
    #pragma unroll
    for (int q = 0; q < KSPLIT; q++)
        s += part[(size_t)q * (B_SZ * NLAB) + idx];
    out[idx] = -sqrtf(s);
}

// ---------------------------------------------------------------------------
// Launch
// ---------------------------------------------------------------------------
extern "C" void kernel_launch(void* const* d_in, const int* in_sizes, int n_in,
                              void* d_out, int out_size)
{
    const float* sbj    = (const float*)d_in[0];
    const float* obj    = (const float*)d_in[1];
    const float* W1     = (const float*)d_in[2];
    const float* b1     = (const float*)d_in[3];
    const float* W2     = (const float*)d_in[4];
    const float* b2     = (const float*)d_in[5];
    const float* labels = (const float*)d_in[6];
    float* out = (float*)d_out;

    float *x_ptr, *hidden_ptr, *emb_ptr, *part_ptr;
    cudaGetSymbolAddress((void**)&x_ptr, g_x);
    cudaGetSymbolAddress((void**)&hidden_ptr, g_hidden);
    cudaGetSymbolAddress((void**)&emb_ptr, g_emb);
    cudaGetSymbolAddress((void**)&part_ptr, g_part);

    cudaFuncSetAttribute(gemm_tc<1>, cudaFuncAttributeMaxDynamicSharedMemorySize, GEMM_SMEM);
    cudaFuncSetAttribute(gemm_tc<0>, cudaFuncAttributeMaxDynamicSharedMemorySize, GEMM_SMEM);
    cudaFuncSetAttribute(scores_part_kernel, cudaFuncAttributeMaxDynamicSharedMemorySize, SC_SMEM);

    relu_cat_kernel<<<(B_SZ * DIN / 4) / 256, 256>>>(sbj, obj, x_ptr);

    dim3 grid(DOUT / BN, B_SZ / BM);   // (16,16) = 256 CTAs
    gemm_tc<1><<<grid, 256, GEMM_SMEM>>>(x_ptr, W1, b1, hidden_ptr, DIN);
    gemm_tc<0><<<grid, 256, GEMM_SMEM>>>(hidden_ptr, W2, b2, emb_ptr, DOUT);

    scores_part_kernel<<<dim3(B_SZ / 8, KSPLIT), 256, SC_SMEM>>>(labels, emb_ptr, part_ptr);
    scores_reduce_kernel<<<(B_SZ * NLAB) / 256, 256>>>(part_ptr, out);
}

// round 15
// speedup vs baseline: 1.0331x; 1.0331x over previous
#include <cuda_runtime.h>
#include <cstdint>

#define B_SZ  1024
#define DHALF 2048
#define DIN   4096
#define DOUT  1024
#define NLAB  128
#define KSPLIT 8

// Scratch (allocation-free rule: __device__ globals)
__device__ float g_x[B_SZ * DIN];               // relu(concat(sbj,obj))
__device__ float g_hidden[B_SZ * DOUT];         // relu(hidden)
__device__ float g_emb[B_SZ * DOUT];            // emb
__device__ float g_part[KSPLIT * B_SZ * NLAB];  // scores split-k partials

// ---------------------------------------------------------------------------
// helpers
// ---------------------------------------------------------------------------
__device__ __forceinline__ uint32_t smem_u32(const void* p) {
    uint32_t a;
    asm("{ .reg .u64 t; cvta.to.shared.u64 t, %1; cvt.u32.u64 %0, t; }"
        : "=r"(a) : "l"(p));
    return a;
}
#define CP16(dst, src) asm volatile("cp.async.cg.shared.global [%0], [%1], 16;" :: "r"(dst), "l"(src) : "memory")
#define CP_COMMIT()    asm volatile("cp.async.commit_group;" ::: "memory")

__device__ __forceinline__ void mma_tf32(float& c0, float& c1, float& c2, float& c3,
                                         uint32_t a0, uint32_t a1, uint32_t a2, uint32_t a3,
                                         uint32_t b0, uint32_t b1) {
    asm volatile(
        "mma.sync.aligned.m16n8k8.row.col.f32.tf32.tf32.f32 "
        "{%0,%1,%2,%3}, {%4,%5,%6,%7}, {%8,%9}, {%0,%1,%2,%3};"
        : "+f"(c0), "+f"(c1), "+f"(c2), "+f"(c3)
        : "r"(a0), "r"(a1), "r"(a2), "r"(a3), "r"(b0), "r"(b1));
}

// ---------------------------------------------------------------------------
// Prepass: g_x[m][k] = relu(concat(sbj,obj))
// ---------------------------------------------------------------------------
__global__ __launch_bounds__(256)
void relu_cat_kernel(const float* __restrict__ sbj, const float* __restrict__ obj,
                     float* __restrict__ x)
{
    const int idx = blockIdx.x * 256 + threadIdx.x;
    const int row = idx >> 10;
    const int c4  = idx & 1023;
    const int col = c4 * 4;
    const float* src = (col < DHALF) ? &sbj[(size_t)row * DHALF + col]
                                     : &obj[(size_t)row * DHALF + col - DHALF];
    float4 v = *reinterpret_cast<const float4*>(src);
    v.x = fmaxf(v.x, 0.f); v.y = fmaxf(v.y, 0.f);
    v.z = fmaxf(v.z, 0.f); v.w = fmaxf(v.w, 0.f);
    *reinterpret_cast<float4*>(&x[(size_t)row * DIN + col]) = v;
}

// ---------------------------------------------------------------------------
// tf32 tensor GEMM: C = act(A @ W + bias)
// CTA tile 128x64 (BM=128 halves A-strip re-reads: L2 traffic -25% vs 64x64),
// 256 threads = 8 warps in 4m x 2n quads, warp tile 32x32 (measured-best
// per-warp shape: per k8 = 16 LDS.32 + 8 HMMA).
// 3-stage cp.async ring, ONE __syncthreads per stage:
//   iter t: wait_group 1 -> sync -> issue(t+2) -> commit -> mma(t)
// Bank-clean: As stride 36 (4*l4+lq perm), Bs stride 72 (8*lq+l4 perm).
// Grid (16, 8) = 128 CTAs -> 1 CTA/SM, 2 warps/SMSP resident.
// ---------------------------------------------------------------------------
#define BM 128
#define BN 64
#define BK 32
#define AS_STR 36
#define BS_STR 72
#define AS_SZ  (BM * AS_STR)        // 4608 floats
#define BS_SZ  (BK * BS_STR)        // 2304 floats
#define STG_FL (AS_SZ + BS_SZ)      // 6912 floats
#define STG_BY (STG_FL * 4)         // 27648 bytes
#define NSTAGE 3
#define GEMM_SMEM (NSTAGE * STG_BY) // 82944

template <int RELU>
__global__ __launch_bounds__(256, 1)
void gemm_tc(const float* __restrict__ A, const float* __restrict__ Wmat,
             const float* __restrict__ bias, float* __restrict__ Cout, int K)
{
    extern __shared__ float sm[];
    const int T = K / BK;

    const int tid  = threadIdx.x;
    const int wid  = tid >> 5;
    const int lane = tid & 31;
    const int lq   = lane & 3;
    const int l4   = lane >> 2;

    const int m0 = blockIdx.y * BM;
    const int n0 = blockIdx.x * BN;
    const int wm = (wid >> 1) * 32;   // 4 m-quads: 0,32,64,96
    const int wn = (wid & 1) * 32;    // 2 n-quads: 0,32

    // fills with 256 threads: A tile 128r x 8 f4 = 1024 f4 -> 4/thread
    //                         B tile  32r x 16 f4 =  512 f4 -> 2/thread
    const int ar = tid >> 3, ac = tid & 7;     // A rows ar+32j, j=0..3
    const int br = tid >> 4, bc = tid & 15;    // B rows br, br+16

    const uint32_t smBase = smem_u32(sm);
    uint32_t aD[4], bD[2];
    #pragma unroll
    for (int j = 0; j < 4; j++)
        aD[j] = smBase + (uint32_t)((ar + 32 * j) * AS_STR + ac * 4) * 4;
    bD[0] = smBase + (uint32_t)(AS_SZ + br * BS_STR + bc * 4) * 4;
    bD[1] = smBase + (uint32_t)(AS_SZ + (br + 16) * BS_STR + bc * 4) * 4;

    const float* aS = &A[(size_t)(m0 + ar) * K + ac * 4];       // +32j rows
    const float* bS0 = &Wmat[(size_t)br * DOUT + n0 + bc * 4];
    const float* bS1 = &Wmat[(size_t)(br + 16) * DOUT + n0 + bc * 4];

    auto issue = [&](int s) {
        const uint32_t off = (uint32_t)s * STG_BY;
        #pragma unroll
        for (int j = 0; j < 4; j++)
            CP16(aD[j] + off, aS + (size_t)(32 * j) * K);
        CP16(bD[0] + off, bS0);
        CP16(bD[1] + off, bS1);
        aS += BK;
        bS0 += (size_t)BK * DOUT; bS1 += (size_t)BK * DOUT;
    };

    float acc[2][4][4];
    #pragma unroll
    for (int mi = 0; mi < 2; mi++)
        #pragma unroll
        for (int nj = 0; nj < 4; nj++)
            #pragma unroll
            for (int r = 0; r < 4; r++) acc[mi][nj][r] = 0.f;

    issue(0); CP_COMMIT();
    issue(1); CP_COMMIT();

    int buf = 0, sNext = 2;

    for (int t = 0; t < T; t++) {
        asm volatile("cp.async.wait_group 1;" ::: "memory");
        __syncthreads();

        if (t + 2 < T) issue(sNext);
        CP_COMMIT();    // exactly one group per iteration

        const float* Ab = sm + buf * STG_FL;
        const float* Bb = Ab + AS_SZ;

        #pragma unroll
        for (int k8 = 0; k8 < BK; k8 += 8) {
            uint32_t a[2][4];
            #pragma unroll
            for (int mi = 0; mi < 2; mi++) {
                const int R = wm + mi * 16 + l4;
                a[mi][0] = __float_as_uint(Ab[R * AS_STR + k8 + lq]);
                a[mi][1] = __float_as_uint(Ab[(R + 8) * AS_STR + k8 + lq]);
                a[mi][2] = __float_as_uint(Ab[R * AS_STR + k8 + lq + 4]);
                a[mi][3] = __float_as_uint(Ab[(R + 8) * AS_STR + k8 + lq + 4]);
            }
            uint32_t b[4][2];
            #pragma unroll
            for (int nj = 0; nj < 4; nj++) {
                const int Cn = wn + nj * 8 + l4;
                b[nj][0] = __float_as_uint(Bb[(k8 + lq) * BS_STR + Cn]);
                b[nj][1] = __float_as_uint(Bb[(k8 + lq + 4) * BS_STR + Cn]);
            }
            #pragma unroll
            for (int mi = 0; mi < 2; mi++)
                #pragma unroll
                for (int nj = 0; nj < 4; nj++)
                    mma_tf32(acc[mi][nj][0], acc[mi][nj][1],
                             acc[mi][nj][2], acc[mi][nj][3],
                             a[mi][0], a[mi][1], a[mi][2], a[mi][3],
                             b[nj][0], b[nj][1]);
        }

        buf   = (buf == NSTAGE - 1) ? 0 : buf + 1;
        sNext = (sNext == NSTAGE - 1) ? 0 : sNext + 1;
    }

    // epilogue: bias (+relu)
    #pragma unroll
    for (int mi = 0; mi < 2; mi++) {
        #pragma unroll
        for (int nj = 0; nj < 4; nj++) {
            const int col = n0 + wn + nj * 8 + lq * 2;
            const float bb0 = bias[col];
            const float bb1 = bias[col + 1];
            const int row = m0 + wm + mi * 16 + l4;
            float o0 = acc[mi][nj][0] + bb0;
            float o1 = acc[mi][nj][1] + bb1;
            float o2 = acc[mi][nj][2] + bb0;
            float o3 = acc[mi][nj][3] + bb1;
            if (RELU) {
                o0 = fmaxf(o0, 0.f); o1 = fmaxf(o1, 0.f);
                o2 = fmaxf(o2, 0.f); o3 = fmaxf(o3, 0.f);
            }
            float2 p0 = {o0, o1};
            float2 p1 = {o2, o3};
            *reinterpret_cast<float2*>(&Cout[(size_t)row * DOUT + col])       = p0;
            *reinterpret_cast<float2*>(&Cout[(size_t)(row + 8) * DOUT + col]) = p1;
        }
    }
}

// ---------------------------------------------------------------------------
// Scores split-k x8 (unchanged, near math floor): partial[q][b][l]
// ---------------------------------------------------------------------------
#define LS_STR 68
#define SC_STG (NLAB * LS_STR + 8 * LS_STR)     // 9248 floats
#define SC_SMEM (2 * SC_STG * 4)                // 73984 bytes
#define NCHUNK_Q ((DOUT / KSPLIT) / 64)         // 2

__global__ __launch_bounds__(256)
void scores_part_kernel(const float* __restrict__ labels,
                        const float* __restrict__ emb,
                        float* __restrict__ part)
{
    extern __shared__ float sm[];
    const int tid = threadIdx.x;
    const int b0  = blockIdx.x * 8;
    const int kh  = blockIdx.y * (DOUT / KSPLIT);
    const int l   = tid & 127;
    const int bg  = tid >> 7;

    const uint32_t smBase = smem_u32(sm);
    const int lr = tid >> 4, lc = tid & 15;

    auto issue = [&](int c, int buf) {
        const int k0 = kh + c * 64;
        const uint32_t off = (uint32_t)buf * (SC_STG * 4);
        #pragma unroll
        for (int j = 0; j < 8; j++) {
            const int row = lr + j * 16;
            CP16(smBase + off + (uint32_t)(row * LS_STR + lc * 4) * 4,
                 &labels[(size_t)row * DOUT + k0 + lc * 4]);
        }
        if (tid < 128) {
            const int row = tid >> 4, c4 = tid & 15;
            CP16(smBase + off + (uint32_t)(NLAB * LS_STR + row * LS_STR + c4 * 4) * 4,
                 &emb[(size_t)(b0 + row) * DOUT + k0 + c4 * 4]);
        }
    };

    float acc0 = 0.f, acc1 = 0.f, acc2 = 0.f, acc3 = 0.f;

    issue(0, 0); CP_COMMIT();

    for (int c = 0; c < NCHUNK_Q; c++) {
        const int buf = c & 1;
        if (c + 1 < NCHUNK_Q) { issue(c + 1, buf ^ 1); }
        CP_COMMIT();
        asm volatile("cp.async.wait_group 1;" ::: "memory");
        __syncthreads();

        const float* Sb = sm + buf * SC_STG;
        const float4* Lp = reinterpret_cast<const float4*>(Sb + l * LS_STR);
        const float* Ep = Sb + NLAB * LS_STR + (bg * 4) * LS_STR;

        #pragma unroll
        for (int k4 = 0; k4 < 16; k4++) {
            const float4 lv = Lp[k4];
            const float4 e0 = *reinterpret_cast<const float4*>(Ep + 0 * LS_STR + k4 * 4);
            const float4 e1 = *reinterpret_cast<const float4*>(Ep + 1 * LS_STR + k4 * 4);
            const float4 e2 = *reinterpret_cast<const float4*>(Ep + 2 * LS_STR + k4 * 4);
            const float4 e3 = *reinterpret_cast<const float4*>(Ep + 3 * LS_STR + k4 * 4);
            float d;
            d = fmaxf(lv.x - e0.x, 0.f); acc0 = fmaf(d, d, acc0);
            d = fmaxf(lv.y - e0.y, 0.f); acc0 = fmaf(d, d, acc0);
            d = fmaxf(lv.z - e0.z, 0.f); acc0 = fmaf(d, d, acc0);
            d = fmaxf(lv.w - e0.w, 0.f); acc0 = fmaf(d, d, acc0);
            d = fmaxf(lv.x - e1.x, 0.f); acc1 = fmaf(d, d, acc1);
            d = fmaxf(lv.y - e1.y, 0.f); acc1 = fmaf(d, d, acc1);
            d = fmaxf(lv.z - e1.z, 0.f); acc1 = fmaf(d, d, acc1);
            d = fmaxf(lv.w - e1.w, 0.f); acc1 = fmaf(d, d, acc1);
            d = fmaxf(lv.x - e2.x, 0.f); acc2 = fmaf(d, d, acc2);
            d = fmaxf(lv.y - e2.y, 0.f); acc2 = fmaf(d, d, acc2);
            d = fmaxf(lv.z - e2.z, 0.f); acc2 = fmaf(d, d, acc2);
            d = fmaxf(lv.w - e2.w, 0.f); acc2 = fmaf(d, d, acc2);
            d = fmaxf(lv.x - e3.x, 0.f); acc3 = fmaf(d, d, acc3);
            d = fmaxf(lv.y - e3.y, 0.f); acc3 = fmaf(d, d, acc3);
            d = fmaxf(lv.z - e3.z, 0.f); acc3 = fmaf(d, d, acc3);
            d = fmaxf(lv.w - e3.w, 0.f); acc3 = fmaf(d, d, acc3);
        }
        __syncthreads();
    }

    float* dst = part + (size_t)blockIdx.y * (B_SZ * NLAB);
    dst[(size_t)(b0 + bg * 4 + 0) * NLAB + l] = acc0;
    dst[(size_t)(b0 + bg * 4 + 1) * NLAB + l] = acc1;
    dst[(size_t)(b0 + bg * 4 + 2) * NLAB + l] = acc2;
    dst[(size_t)(b0 + bg * 4 + 3) * NLAB + l] = acc3;
}

__global__ __launch_bounds__(256)
void scores_reduce_kernel(const float* __restrict__ part, float* __restrict__ out)
{
    const int idx = blockIdx.x * 256 + threadIdx.x;   // 0 .. 131071
    float s = 0.f;
    #pragma unroll
    for (int q = 0; q < KSPLIT; q++)
        s += part[(size_t)q * (B_SZ * NLAB) + idx];
    out[idx] = -sqrtf(s);
}

// ---------------------------------------------------------------------------
// Launch
// ---------------------------------------------------------------------------
extern "C" void kernel_launch(void* const* d_in, const int* in_sizes, int n_in,
                              void* d_out, int out_size)
{
    const float* sbj    = (const float*)d_in[0];
    const float* obj    = (const float*)d_in[1];
    const float* W1     = (const float*)d_in[2];
    const float* b1     = (const float*)d_in[3];
    const float* W2     = (const float*)d_in[4];
    const float* b2     = (const float*)d_in[5];
    const float* labels = (const float*)d_in[6];
    float* out = (float*)d_out;

    float *x_ptr, *hidden_ptr, *emb_ptr, *part_ptr;
    cudaGetSymbolAddress((void**)&x_ptr, g_x);
    cudaGetSymbolAddress((void**)&hidden_ptr, g_hidden);
    cudaGetSymbolAddress((void**)&emb_ptr, g_emb);
    cudaGetSymbolAddress((void**)&part_ptr, g_part);

    cudaFuncSetAttribute(gemm_tc<1>, cudaFuncAttributeMaxDynamicSharedMemorySize, GEMM_SMEM);
    cudaFuncSetAttribute(gemm_tc<0>, cudaFuncAttributeMaxDynamicSharedMemorySize, GEMM_SMEM);
    cudaFuncSetAttribute(scores_part_kernel, cudaFuncAttributeMaxDynamicSharedMemorySize, SC_SMEM);

    relu_cat_kernel<<<(B_SZ * DIN / 4) / 256, 256>>>(sbj, obj, x_ptr);

    dim3 grid(DOUT / BN, B_SZ / BM);   // (16, 8) = 128 CTAs
    gemm_tc<1><<<grid, 256, GEMM_SMEM>>>(x_ptr, W1, b1, hidden_ptr, DIN);
    gemm_tc<0><<<grid, 256, GEMM_SMEM>>>(hidden_ptr, W2, b2, emb_ptr, DOUT);

    scores_part_kernel<<<dim3(B_SZ / 8, KSPLIT), 256, SC_SMEM>>>(labels, emb_ptr, part_ptr);
    scores_reduce_kernel<<<(B_SZ * NLAB) / 256, 256>>>(part_ptr, out);
}

// round 16
// speedup vs baseline: 1.0507x; 1.0171x over previous
#include <cuda_runtime.h>
#include <cstdint>

#define B_SZ  1024
#define DHALF 2048
#define DIN   4096
#define DOUT  1024
#define NLAB  128
#define KSPLIT 8

// Scratch (allocation-free rule: __device__ globals)
__device__ float g_x[B_SZ * DIN];               // relu(concat(sbj,obj))
__device__ float g_hidden[B_SZ * DOUT];         // relu(hidden)
__device__ float g_emb[B_SZ * DOUT];            // emb
__device__ float g_part[KSPLIT * B_SZ * NLAB];  // scores split-k partials

// ---------------------------------------------------------------------------
// helpers
// ---------------------------------------------------------------------------
__device__ __forceinline__ uint32_t smem_u32(const void* p) {
    uint32_t a;
    asm("{ .reg .u64 t; cvta.to.shared.u64 t, %1; cvt.u32.u64 %0, t; }"
        : "=r"(a) : "l"(p));
    return a;
}
#define CP16(dst, src) asm volatile("cp.async.cg.shared.global [%0], [%1], 16;" :: "r"(dst), "l"(src) : "memory")
#define CP_COMMIT()    asm volatile("cp.async.commit_group;" ::: "memory")

__device__ __forceinline__ void mma_tf32(float& c0, float& c1, float& c2, float& c3,
                                         uint32_t a0, uint32_t a1, uint32_t a2, uint32_t a3,
                                         uint32_t b0, uint32_t b1) {
    asm volatile(
        "mma.sync.aligned.m16n8k8.row.col.f32.tf32.tf32.f32 "
        "{%0,%1,%2,%3}, {%4,%5,%6,%7}, {%8,%9}, {%0,%1,%2,%3};"
        : "+f"(c0), "+f"(c1), "+f"(c2), "+f"(c3)
        : "r"(a0), "r"(a1), "r"(a2), "r"(a3), "r"(b0), "r"(b1));
}

// packed f32x2 square-accumulate (FFMA2 — PTX-only path, validated in R1)
__device__ __forceinline__ unsigned long long pack2(float lo, float hi) {
    unsigned long long r;
    asm("mov.b64 %0, {%1, %2};" : "=l"(r)
        : "r"(__float_as_uint(lo)), "r"(__float_as_uint(hi)));
    return r;
}
__device__ __forceinline__ void ffma2_sq(unsigned long long& acc, unsigned long long d) {
    asm("fma.rn.f32x2 %0, %1, %2, %0;" : "+l"(acc) : "l"(d), "l"(d));
}
__device__ __forceinline__ float2 unpack2(unsigned long long p) {
    uint32_t lo, hi;
    asm("mov.b64 {%0, %1}, %2;" : "=r"(lo), "=r"(hi) : "l"(p));
    return make_float2(__uint_as_float(lo), __uint_as_float(hi));
}

// ---------------------------------------------------------------------------
// Prepass: g_x[m][k] = relu(concat(sbj,obj))
// ---------------------------------------------------------------------------
__global__ __launch_bounds__(256)
void relu_cat_kernel(const float* __restrict__ sbj, const float* __restrict__ obj,
                     float* __restrict__ x)
{
    const int idx = blockIdx.x * 256 + threadIdx.x;
    const int row = idx >> 10;
    const int c4  = idx & 1023;
    const int col = c4 * 4;
    const float* src = (col < DHALF) ? &sbj[(size_t)row * DHALF + col]
                                     : &obj[(size_t)row * DHALF + col - DHALF];
    float4 v = *reinterpret_cast<const float4*>(src);
    v.x = fmaxf(v.x, 0.f); v.y = fmaxf(v.y, 0.f);
    v.z = fmaxf(v.z, 0.f); v.w = fmaxf(v.w, 0.f);
    *reinterpret_cast<float4*>(&x[(size_t)row * DIN + col]) = v;
}

// ---------------------------------------------------------------------------
// tf32 tensor GEMM (R13 measured-best, restored exactly):
// CTA tile 64x64, 128 threads = 4 warps (2m x 2n), warp tile 32x32:
// per k8 per warp: 16 LDS + 8 HMMA (2:1).
// 3-stage cp.async ring, ONE __syncthreads per stage.
// Bank-clean: As stride 36 (4*l4+lq perm), Bs stride 72 (8*lq+l4 perm).
// __launch_bounds__(128,4): 4 CTAs/SM possible, smem 54KB/CTA.
// ---------------------------------------------------------------------------
#define BM 64
#define BN 64
#define BK 32
#define AS_STR 36
#define BS_STR 72
#define AS_SZ  (BM * AS_STR)
#define BS_SZ  (BK * BS_STR)
#define STG_FL (AS_SZ + BS_SZ)      // 4608 floats
#define STG_BY (STG_FL * 4)         // 18432 bytes
#define NSTAGE 3
#define GEMM_SMEM (NSTAGE * STG_BY) // 55296

template <int RELU>
__global__ __launch_bounds__(128, 4)
void gemm_tc(const float* __restrict__ A, const float* __restrict__ Wmat,
             const float* __restrict__ bias, float* __restrict__ Cout, int K)
{
    extern __shared__ float sm[];
    const int T = K / BK;

    const int tid  = threadIdx.x;
    const int wid  = tid >> 5;
    const int lane = tid & 31;
    const int lq   = lane & 3;
    const int l4   = lane >> 2;

    const int m0 = blockIdx.y * BM;
    const int n0 = blockIdx.x * BN;
    const int wm = (wid >> 1) * 32;
    const int wn = (wid & 1) * 32;

    const int ar = tid >> 3, ac = tid & 7;
    const int br = tid >> 4, bc = tid & 15;

    const uint32_t smBase = smem_u32(sm);
    uint32_t aD[4], bD[4];
    #pragma unroll
    for (int j = 0; j < 4; j++) {
        aD[j] = smBase + (uint32_t)((ar + 16 * j) * AS_STR + ac * 4) * 4;
        bD[j] = smBase + (uint32_t)(AS_SZ + (br + 8 * j) * BS_STR + bc * 4) * 4;
    }

    const float* aS = &A[(size_t)(m0 + ar) * K + ac * 4];
    const float* bS = &Wmat[(size_t)br * DOUT + n0 + bc * 4];

    auto issue = [&](int s) {
        const uint32_t off = (uint32_t)s * STG_BY;
        #pragma unroll
        for (int j = 0; j < 4; j++)
            CP16(aD[j] + off, aS + (size_t)(16 * j) * K);
        #pragma unroll
        for (int j = 0; j < 4; j++)
            CP16(bD[j] + off, bS + (size_t)(8 * j) * DOUT);
        aS += BK;
        bS += (size_t)BK * DOUT;
    };

    float acc[2][4][4];
    #pragma unroll
    for (int mi = 0; mi < 2; mi++)
        #pragma unroll
        for (int nj = 0; nj < 4; nj++)
            #pragma unroll
            for (int r = 0; r < 4; r++) acc[mi][nj][r] = 0.f;

    issue(0); CP_COMMIT();
    issue(1); CP_COMMIT();

    int buf = 0, sNext = 2;

    for (int t = 0; t < T; t++) {
        asm volatile("cp.async.wait_group 1;" ::: "memory");
        __syncthreads();

        if (t + 2 < T) issue(sNext);
        CP_COMMIT();    // exactly one group per iteration

        const float* Ab = sm + buf * STG_FL;
        const float* Bb = Ab + AS_SZ;

        #pragma unroll
        for (int k8 = 0; k8 < BK; k8 += 8) {
            uint32_t a[2][4];
            #pragma unroll
            for (int mi = 0; mi < 2; mi++) {
                const int R = wm + mi * 16 + l4;
                a[mi][0] = __float_as_uint(Ab[R * AS_STR + k8 + lq]);
                a[mi][1] = __float_as_uint(Ab[(R + 8) * AS_STR + k8 + lq]);
                a[mi][2] = __float_as_uint(Ab[R * AS_STR + k8 + lq + 4]);
                a[mi][3] = __float_as_uint(Ab[(R + 8) * AS_STR + k8 + lq + 4]);
            }
            uint32_t b[4][2];
            #pragma unroll
            for (int nj = 0; nj < 4; nj++) {
                const int Cn = wn + nj * 8 + l4;
                b[nj][0] = __float_as_uint(Bb[(k8 + lq) * BS_STR + Cn]);
                b[nj][1] = __float_as_uint(Bb[(k8 + lq + 4) * BS_STR + Cn]);
            }
            #pragma unroll
            for (int mi = 0; mi < 2; mi++)
                #pragma unroll
                for (int nj = 0; nj < 4; nj++)
                    mma_tf32(acc[mi][nj][0], acc[mi][nj][1],
                             acc[mi][nj][2], acc[mi][nj][3],
                             a[mi][0], a[mi][1], a[mi][2], a[mi][3],
                             b[nj][0], b[nj][1]);
        }

        buf   = (buf == NSTAGE - 1) ? 0 : buf + 1;
        sNext = (sNext == NSTAGE - 1) ? 0 : sNext + 1;
    }

    // epilogue: bias (+relu)
    #pragma unroll
    for (int mi = 0; mi < 2; mi++) {
        #pragma unroll
        for (int nj = 0; nj < 4; nj++) {
            const int col = n0 + wn + nj * 8 + lq * 2;
            const float bb0 = bias[col];
            const float bb1 = bias[col + 1];
            const int row = m0 + wm + mi * 16 + l4;
            float o0 = acc[mi][nj][0] + bb0;
            float o1 = acc[mi][nj][1] + bb1;
            float o2 = acc[mi][nj][2] + bb0;
            float o3 = acc[mi][nj][3] + bb1;
            if (RELU) {
                o0 = fmaxf(o0, 0.f); o1 = fmaxf(o1, 0.f);
                o2 = fmaxf(o2, 0.f); o3 = fmaxf(o3, 0.f);
            }
            float2 p0 = {o0, o1};
            float2 p1 = {o2, o3};
            *reinterpret_cast<float2*>(&Cout[(size_t)row * DOUT + col])       = p0;
            *reinterpret_cast<float2*>(&Cout[(size_t)(row + 8) * DOUT + col]) = p1;
        }
    }
}

// ---------------------------------------------------------------------------
// Scores split-k x8 with packed FFMA2 square-accumulate:
// per k4 (16 elems): 16 FADD + 16 FMNMX + 8 PACK + 8 FFMA2
//   -> fma-class 24 (was 32), alu-class 24 (was 16): balanced pipes.
// Accumulators: 4 rows x 2 f32x2 pairs; horizontal sum at the end.
// ---------------------------------------------------------------------------
#define LS_STR 68
#define SC_STG (NLAB * LS_STR + 8 * LS_STR)     // 9248 floats
#define SC_SMEM (2 * SC_STG * 4)                // 73984 bytes
#define NCHUNK_Q ((DOUT / KSPLIT) / 64)         // 2

__global__ __launch_bounds__(256)
void scores_part_kernel(const float* __restrict__ labels,
                        const float* __restrict__ emb,
                        float* __restrict__ part)
{
    extern __shared__ float sm[];
    const int tid = threadIdx.x;
    const int b0  = blockIdx.x * 8;
    const int kh  = blockIdx.y * (DOUT / KSPLIT);
    const int l   = tid & 127;
    const int bg  = tid >> 7;

    const uint32_t smBase = smem_u32(sm);
    const int lr = tid >> 4, lc = tid & 15;

    auto issue = [&](int c, int buf) {
        const int k0 = kh + c * 64;
        const uint32_t off = (uint32_t)buf * (SC_STG * 4);
        #pragma unroll
        for (int j = 0; j < 8; j++) {
            const int row = lr + j * 16;
            CP16(smBase + off + (uint32_t)(row * LS_STR + lc * 4) * 4,
                 &labels[(size_t)row * DOUT + k0 + lc * 4]);
        }
        if (tid < 128) {
            const int row = tid >> 4, c4 = tid & 15;
            CP16(smBase + off + (uint32_t)(NLAB * LS_STR + row * LS_STR + c4 * 4) * 4,
                 &emb[(size_t)(b0 + row) * DOUT + k0 + c4 * 4]);
        }
    };

    unsigned long long acc[4][2];
    #pragma unroll
    for (int r = 0; r < 4; r++) { acc[r][0] = 0ull; acc[r][1] = 0ull; }

    issue(0, 0); CP_COMMIT();

    for (int c = 0; c < NCHUNK_Q; c++) {
        const int buf = c & 1;
        if (c + 1 < NCHUNK_Q) { issue(c + 1, buf ^ 1); }
        CP_COMMIT();
        asm volatile("cp.async.wait_group 1;" ::: "memory");
        __syncthreads();

        const float* Sb = sm + buf * SC_STG;
        const float4* Lp = reinterpret_cast<const float4*>(Sb + l * LS_STR);
        const float* Ep = Sb + NLAB * LS_STR + (bg * 4) * LS_STR;

        #pragma unroll
        for (int k4 = 0; k4 < 16; k4++) {
            const float4 lv = Lp[k4];
            #pragma unroll
            for (int r = 0; r < 4; r++) {
                const float4 ev = *reinterpret_cast<const float4*>(
                    Ep + r * LS_STR + k4 * 4);
                float x0 = fmaxf(lv.x - ev.x, 0.f);
                float x1 = fmaxf(lv.y - ev.y, 0.f);
                float x2 = fmaxf(lv.z - ev.z, 0.f);
                float x3 = fmaxf(lv.w - ev.w, 0.f);
                ffma2_sq(acc[r][0], pack2(x0, x1));
                ffma2_sq(acc[r][1], pack2(x2, x3));
            }
        }
        __syncthreads();
    }

    float* dst = part + (size_t)blockIdx.y * (B_SZ * NLAB);
    #pragma unroll
    for (int r = 0; r < 4; r++) {
        float2 a0 = unpack2(acc[r][0]);
        float2 a1 = unpack2(acc[r][1]);
        dst[(size_t)(b0 + bg * 4 + r) * NLAB + l] = (a0.x + a0.y) + (a1.x + a1.y);
    }
}

__global__ __launch_bounds__(256)
void scores_reduce_kernel(const float* __restrict__ part, float* __restrict__ out)
{
    const int idx = blockIdx.x * 256 + threadIdx.x;   // 0 .. 131071
    float s = 0.f;
    #pragma unroll
    for (int q = 0; q < KSPLIT; q++)
        s += part[(size_t)q * (B_SZ * NLAB) + idx];
    out[idx] = -sqrtf(s);
}

// ---------------------------------------------------------------------------
// Launch
// ---------------------------------------------------------------------------
extern "C" void kernel_launch(void* const* d_in, const int* in_sizes, int n_in,
                              void* d_out, int out_size)
{
    const float* sbj    = (const float*)d_in[0];
    const float* obj    = (const float*)d_in[1];
    const float* W1     = (const float*)d_in[2];
    const float* b1     = (const float*)d_in[3];
    const float* W2     = (const float*)d_in[4];
    const float* b2     = (const float*)d_in[5];
    const float* labels = (const float*)d_in[6];
    float* out = (float*)d_out;

    float *x_ptr, *hidden_ptr, *emb_ptr, *part_ptr;
    cudaGetSymbolAddress((void**)&x_ptr, g_x);
    cudaGetSymbolAddress((void**)&hidden_ptr, g_hidden);
    cudaGetSymbolAddress((void**)&emb_ptr, g_emb);
    cudaGetSymbolAddress((void**)&part_ptr, g_part);

    cudaFuncSetAttribute(gemm_tc<1>, cudaFuncAttributeMaxDynamicSharedMemorySize, GEMM_SMEM);
    cudaFuncSetAttribute(gemm_tc<0>, cudaFuncAttributeMaxDynamicSharedMemorySize, GEMM_SMEM);
    cudaFuncSetAttribute(scores_part_kernel, cudaFuncAttributeMaxDynamicSharedMemorySize, SC_SMEM);

    relu_cat_kernel<<<(B_SZ * DIN / 4) / 256, 256>>>(sbj, obj, x_ptr);

    dim3 grid(DOUT / BN, B_SZ / BM);   // (16,16) = 256 CTAs
    gemm_tc<1><<<grid, 128, GEMM_SMEM>>>(x_ptr, W1, b1, hidden_ptr, DIN);
    gemm_tc<0><<<grid, 128, GEMM_SMEM>>>(hidden_ptr, W2, b2, emb_ptr, DOUT);

    scores_part_kernel<<<dim3(B_SZ / 8, KSPLIT), 256, SC_SMEM>>>(labels, emb_ptr, part_ptr);
    scores_reduce_kernel<<<(B_SZ * NLAB) / 256, 256>>>(part_ptr, out);
}